// round 9
// baseline (speedup 1.0000x reference)
#include <cuda_runtime.h>
#include <cuda_bf16.h>
#include <mma.h>
#include <cstdint>

using namespace nvcuda;

// Problem constants (GCNLayer_80633716015334)
#define N_NODES   40000
#define N_FEATS   128
#define N_EDGES   640000
#define CAP       96          // bucket capacity; E/N = 16 avg (Poisson), P(deg>=96) ~ 1e-40

// ---------------- device scratch (no allocs allowed) ----------------
// g_cursor is zero at module load; agg_kernel restores the zero-invariant
// every call, so every kernel_launch (incl. graph replays) sees cursor == 0.
__device__ int g_cursor[N_NODES];
__device__ int g_bucket[(size_t)N_NODES * CAP];   // src ids, 15.4 MB

// ---------------- bucket fill (single CSR-build kernel) ----------------
__global__ void fill_bucket(const int* __restrict__ src,
                            const int* __restrict__ dst, int E) {
    int i = blockIdx.x * blockDim.x + threadIdx.x;
    int e4 = i * 4;
    if (e4 + 4 <= E) {
        int4 d = *(const int4*)(dst + e4);
        int4 s = *(const int4*)(src + e4);
        int p0 = atomicAdd(&g_cursor[d.x], 1);
        int p1 = atomicAdd(&g_cursor[d.y], 1);
        int p2 = atomicAdd(&g_cursor[d.z], 1);
        int p3 = atomicAdd(&g_cursor[d.w], 1);
        if (p0 < CAP) g_bucket[(size_t)d.x * CAP + p0] = s.x;
        if (p1 < CAP) g_bucket[(size_t)d.y * CAP + p1] = s.y;
        if (p2 < CAP) g_bucket[(size_t)d.z * CAP + p2] = s.z;
        if (p3 < CAP) g_bucket[(size_t)d.w * CAP + p3] = s.w;
    } else {
        for (int e = e4; e < E; e++) {
            int dd = dst[e];
            int p = atomicAdd(&g_cursor[dd], 1);
            if (p < CAP) g_bucket[(size_t)dd * CAP + p] = src[e];
        }
    }
}

// ---------------- aggregation: one warp per dst node ----------------
__global__ void agg_kernel(const float* __restrict__ h,
                           float* __restrict__ agg, int n) {
    const int lane = threadIdx.x & 31;
    const int warp = (blockIdx.x * blockDim.x + threadIdx.x) >> 5;
    if (warp >= n) return;

    int deg = g_cursor[warp];
    if (deg > CAP) deg = CAP;

    float4 acc = make_float4(0.f, 0.f, 0.f, 0.f);
    const float4* __restrict__ h4 = (const float4*)h;
    const int* __restrict__ bkt = g_bucket + (size_t)warp * CAP;

    for (int cb = 0; cb < deg; cb += 32) {
        int myidx = cb + lane;
        int mysrc = (myidx < deg) ? bkt[myidx] : 0;   // coalesced
        int cnt = deg - cb; if (cnt > 32) cnt = 32;
        int j = 0;
        for (; j + 3 < cnt; j += 4) {
            int s0 = __shfl_sync(0xFFFFFFFFu, mysrc, j);
            int s1 = __shfl_sync(0xFFFFFFFFu, mysrc, j + 1);
            int s2 = __shfl_sync(0xFFFFFFFFu, mysrc, j + 2);
            int s3 = __shfl_sync(0xFFFFFFFFu, mysrc, j + 3);
            float4 v0 = __ldg(&h4[(size_t)s0 * 32 + lane]);
            float4 v1 = __ldg(&h4[(size_t)s1 * 32 + lane]);
            float4 v2 = __ldg(&h4[(size_t)s2 * 32 + lane]);
            float4 v3 = __ldg(&h4[(size_t)s3 * 32 + lane]);
            acc.x += v0.x; acc.y += v0.y; acc.z += v0.z; acc.w += v0.w;
            acc.x += v1.x; acc.y += v1.y; acc.z += v1.z; acc.w += v1.w;
            acc.x += v2.x; acc.y += v2.y; acc.z += v2.z; acc.w += v2.w;
            acc.x += v3.x; acc.y += v3.y; acc.z += v3.z; acc.w += v3.w;
        }
        for (; j < cnt; j++) {
            int s0 = __shfl_sync(0xFFFFFFFFu, mysrc, j);
            float4 v0 = __ldg(&h4[(size_t)s0 * 32 + lane]);
            acc.x += v0.x; acc.y += v0.y; acc.z += v0.z; acc.w += v0.w;
        }
    }
    ((float4*)agg)[(size_t)warp * 32 + lane] = acc;

    if (lane == 0) g_cursor[warp] = 0;   // restore zero-invariant
}

// ============== wmma bf16-split GEMM: out = h @ W^T + b ==============
// fp32 x = hi(bf16) + lo(bf16, exact residual);
// x*y ~= xh*yh + xh*yl + xl*yh  (drop lo*lo -> ~1e-5 rel err, fp32 accum)
// 128x128 tile/CTA, 8 warps, each warp 32x64 via 16x16x16 wmma fragments.

#define LDT 136                         // halves per smem tile row (16B-aligned, conflict-free LDSM)
#define TILE_B (128 * LDT * 2)          // 34816 bytes per tile
#define OFF_AHI 0
#define OFF_ALO (OFF_AHI + TILE_B)
#define OFF_BHI (OFF_ALO + TILE_B)
#define OFF_BLO (OFF_BHI + TILE_B)
#define OFF_BIAS (OFF_BLO + TILE_B)     // 16 rows x 128 f32 (replicated bias)
#define GSMEM_TOTAL (OFF_BIAS + 16 * 128 * 4)

__global__ __launch_bounds__(256, 1)
void gemm_wmma(const float* __restrict__ h, const float* __restrict__ W,
               const float* __restrict__ bias, float* __restrict__ out, int M) {
    extern __shared__ char smem[];
    __nv_bfloat16* Ahi = (__nv_bfloat16*)(smem + OFF_AHI);
    __nv_bfloat16* Alo = (__nv_bfloat16*)(smem + OFF_ALO);
    __nv_bfloat16* Bhi = (__nv_bfloat16*)(smem + OFF_BHI);
    __nv_bfloat16* Blo = (__nv_bfloat16*)(smem + OFF_BLO);
    float* biasT = (float*)(smem + OFF_BIAS);

    const int tid = threadIdx.x;
    const int wid = tid >> 5;
    const int blockM = blockIdx.x * 128;

    // ---- bias tile: 16 identical rows of bias ----
    for (int idx = tid; idx < 16 * 128; idx += 256)
        biasT[idx] = __ldg(bias + (idx & 127));

    // ---- convert: threads 0-127 -> A rows (h tile), 128-255 -> B rows (W) ----
    {
        const int role = tid >> 7;      // 0 = A, 1 = B
        const int row = tid & 127;
        const bool valid = role ? true : (blockM + row < M);
        const float* srcp = role ? (W + (size_t)row * N_FEATS)
                                 : (h + (size_t)(blockM + row) * N_FEATS);
        __nv_bfloat16* hi_t = (role ? Bhi : Ahi) + row * LDT;
        __nv_bfloat16* lo_t = (role ? Blo : Alo) + row * LDT;
#pragma unroll
        for (int kc = 0; kc < 128; kc += 8) {
            float4 v0 = make_float4(0.f, 0.f, 0.f, 0.f), v1 = v0;
            if (valid) {
                v0 = __ldg((const float4*)(srcp + kc));
                v1 = __ldg((const float4*)(srcp + kc + 4));
            }
            float f[8] = {v0.x, v0.y, v0.z, v0.w, v1.x, v1.y, v1.z, v1.w};
            uint32_t hp[4], lp[4];
#pragma unroll
            for (int j = 0; j < 4; j++) {
                __nv_bfloat16 h0 = __float2bfloat16_rn(f[2 * j]);
                __nv_bfloat16 h1 = __float2bfloat16_rn(f[2 * j + 1]);
                float l0 = f[2 * j] - __bfloat162float(h0);
                float l1 = f[2 * j + 1] - __bfloat162float(h1);
                __nv_bfloat162 hh; hh.x = h0; hh.y = h1;
                __nv_bfloat162 ll = __floats2bfloat162_rn(l0, l1);
                hp[j] = *(uint32_t*)&hh;
                lp[j] = *(uint32_t*)&ll;
            }
            *(uint4*)(hi_t + kc) = make_uint4(hp[0], hp[1], hp[2], hp[3]);
            *(uint4*)(lo_t + kc) = make_uint4(lp[0], lp[1], lp[2], lp[3]);
        }
    }
    __syncthreads();

    // ---- warp tiles: wid&3 -> m (4 x 32 rows), wid>>2 -> n (2 x 64 cols) ----
    const int m0 = (wid & 3) * 32;
    const int n0 = (wid >> 2) * 64;

    wmma::fragment<wmma::accumulator, 16, 16, 16, float> acc[2][4];
#pragma unroll
    for (int i = 0; i < 2; i++)
#pragma unroll
        for (int j = 0; j < 4; j++)
            wmma::load_matrix_sync(acc[i][j], biasT + n0 + j * 16, 128,
                                   wmma::mem_row_major);

#pragma unroll
    for (int kk = 0; kk < 8; kk++) {
        const int k = kk * 16;
        wmma::fragment<wmma::matrix_a, 16, 16, 16, __nv_bfloat16, wmma::row_major> ah[2], al[2];
        wmma::fragment<wmma::matrix_b, 16, 16, 16, __nv_bfloat16, wmma::col_major> bh[4], bl[4];
#pragma unroll
        for (int i = 0; i < 2; i++) {
            wmma::load_matrix_sync(ah[i], Ahi + (m0 + i * 16) * LDT + k, LDT);
            wmma::load_matrix_sync(al[i], Alo + (m0 + i * 16) * LDT + k, LDT);
        }
#pragma unroll
        for (int j = 0; j < 4; j++) {
            wmma::load_matrix_sync(bh[j], Bhi + (n0 + j * 16) * LDT + k, LDT);
            wmma::load_matrix_sync(bl[j], Blo + (n0 + j * 16) * LDT + k, LDT);
        }
#pragma unroll
        for (int i = 0; i < 2; i++)
#pragma unroll
            for (int j = 0; j < 4; j++) {
                wmma::mma_sync(acc[i][j], ah[i], bh[j], acc[i][j]);
                wmma::mma_sync(acc[i][j], ah[i], bl[j], acc[i][j]);
                wmma::mma_sync(acc[i][j], al[i], bh[j], acc[i][j]);
            }
    }

    // ---- store (M % 16 == 0, so 16-row tiles are all-or-nothing) ----
#pragma unroll
    for (int i = 0; i < 2; i++) {
        int gm = blockM + m0 + i * 16;
        if (gm < M) {
#pragma unroll
            for (int j = 0; j < 4; j++)
                wmma::store_matrix_sync(out + (size_t)gm * N_FEATS + n0 + j * 16,
                                        acc[i][j], N_FEATS, wmma::mem_row_major);
        }
    }
}

// ---------------- launch ----------------
extern "C" void kernel_launch(void* const* d_in, const int* in_sizes, int n_in,
                              void* d_out, int out_size) {
    const float* h   = (const float*)d_in[0];   // [N, 128]
    const float* W   = (const float*)d_in[1];   // [128, 128]
    const float* b   = (const float*)d_in[2];   // [128]
    const int*  src  = (const int*)d_in[3];     // [E]
    const int*  dst  = (const int*)d_in[4];     // [E]

    const int N = in_sizes[0] / N_FEATS;        // 40000
    const int E = in_sizes[3];                  // 640000

    float* out = (float*)d_out;                       // [N, 128]
    float* agg = (float*)d_out + (size_t)N * N_FEATS; // [N, 128]

    // Allow ~144KB dynamic smem for the wmma GEMM (immediate attribute set,
    // not a captured op).
    cudaFuncSetAttribute(gemm_wmma, cudaFuncAttributeMaxDynamicSharedMemorySize,
                         GSMEM_TOTAL);

    // Fork GEMM onto a second stream (tensor-pipe bound; overlaps the
    // latency-bound fill and the L2-bound agg). No device memory allocated;
    // stream/events leak intentionally (capture-once).
    cudaStream_t s2;
    cudaStreamCreateWithFlags(&s2, cudaStreamNonBlocking);
    cudaEvent_t evFork, evJoin;
    cudaEventCreateWithFlags(&evFork, cudaEventDisableTiming);
    cudaEventCreateWithFlags(&evJoin, cudaEventDisableTiming);

    cudaEventRecord(evFork, 0);
    cudaStreamWaitEvent(s2, evFork, 0);
    {
        int blocks = (N + 127) / 128;   // 313
        gemm_wmma<<<blocks, 256, GSMEM_TOTAL, s2>>>(h, W, b, out, N);
    }
    cudaEventRecord(evJoin, s2);

    // Bucket CSR + aggregation on the capture (default) stream.
    fill_bucket<<<(E / 4 + 255) / 256, 256>>>(src, dst, E);
    {
        int warps_per_block = 8;
        int blocks = (N + warps_per_block - 1) / warps_per_block;
        agg_kernel<<<blocks, warps_per_block * 32>>>(h, agg, N);
    }

    cudaStreamWaitEvent(0, evJoin, 0);
}